// round 5
// baseline (speedup 1.0000x reference)
#include <cuda_runtime.h>
#include <cuda_fp16.h>

#define N_NODES 100000
#define N_EDGES 1600000
#define N_GRAPHS 1024
#define HID 32
#define CAP 128
#define EPSN 1e-5f

#define G_GATHER 740   // 148 SMs x 5 blocks (36 regs x 320 thr caps at 5/SM)
#define G_WIDE   888   // 148 SMs x 6 blocks
#define TBG 320
#define TBY 256

// boundary alignment proofs (warp=32, node-group=4 or 8):
static_assert((G_GATHER * TBG) % 32 == 0 && (N_NODES * 4) % 32 == 0, "");
static_assert(((N_NODES * 4) % (G_GATHER * TBG)) % 32 == 0, "");
static_assert((G_WIDE * TBY) % 32 == 0 && (N_NODES * 8) % 32 == 0, "");
static_assert(((N_NODES * 8) % (G_WIDE * TBY)) % 32 == 0, "");

// ---------------- scratch (device globals; no allocations allowed) ----------
__device__ int    g_deg[N_NODES];
__device__ int    g_b32[N_NODES];
__device__ float  g_dinv[N_NODES];
__device__ float  g_cnt[N_GRAPHS];
__device__ __align__(16)  int   g_csr[(size_t)N_NODES * CAP];
__device__ __align__(128) uint2 g_hq[N_NODES * 8];   // hs = dinv*(x@W), fp16 x4
__device__ float4 g_a[N_NODES * 8];                  // conv output (fp32)
__device__ float4 g_x[N_NODES * 8];                  // layer activations x1/x2
__device__ __align__(16) float g_gs[3][N_GRAPHS * HID];  // per-graph sums
__device__ __align__(16) float g_gv[3][N_GRAPHS * HID];  // per-graph sum-of-squares
__device__ __align__(16) float g_pool[N_GRAPHS * HID];   // pooling sums

// ---------------- helpers ---------------------------------------------------
__device__ __forceinline__ void f4fma(float4& a, float s, float4 v) {
    a.x += s * v.x; a.y += s * v.y; a.z += s * v.z; a.w += s * v.w;
}
__device__ __forceinline__ void f4add(float4& a, float4 v) {
    a.x += v.x; a.y += v.y; a.z += v.z; a.w += v.w;
}
__device__ __forceinline__ int clampN(int v) { return min(max(v, 0), N_NODES - 1); }

__device__ __forceinline__ void unpack2(uint4 q, float4& a, float4& b) {
    float2 p0 = __half22float2(*(__half2*)&q.x);
    float2 p1 = __half22float2(*(__half2*)&q.y);
    float2 p2 = __half22float2(*(__half2*)&q.z);
    float2 p3 = __half22float2(*(__half2*)&q.w);
    a = make_float4(p0.x, p0.y, p1.x, p1.y);
    b = make_float4(p2.x, p2.y, p3.x, p3.y);
}
__device__ __forceinline__ void acc_add2(float4& a, float4& b, uint4 q) {
    float4 u, v; unpack2(q, u, v); f4add(a, u); f4add(b, v);
}
__device__ __forceinline__ uint2 pack_h(float4 v) {
    __half2 lo = __floats2half2_rn(v.x, v.y);
    __half2 hi = __floats2half2_rn(v.z, v.w);
    uint2 q; q.x = *(unsigned*)&lo; q.y = *(unsigned*)&hi; return q;
}

__device__ __forceinline__ void redX(float4& v, int m) {
    v.x += __shfl_xor_sync(0xffffffffu, v.x, m);
    v.y += __shfl_xor_sync(0xffffffffu, v.y, m);
    v.z += __shfl_xor_sync(0xffffffffu, v.z, m);
    v.w += __shfl_xor_sync(0xffffffffu, v.w, m);
}
__device__ __forceinline__ void at4(float* p, float4 v) {
    atomicAdd(p + 0, v.x); atomicAdd(p + 1, v.y);
    atomicAdd(p + 2, v.z); atomicAdd(p + 3, v.w);
}

// seg-add for k_y layout (4 nodes x 8 f4 per warp), single payload.
__device__ __forceinline__ void seg_add(float* base, int g, float4 v) {
    unsigned lane = threadIdx.x & 31u;
    int g0 = __shfl_sync(0xffffffffu, g, 0);
    if (__all_sync(0xffffffffu, g == g0)) {
        redX(v, 8); redX(v, 16);
        if (lane < 8) at4(base + (size_t)g * HID + lane * 4, v);
    } else {
        at4(base + (size_t)g * HID + (lane & 7u) * 4, v);
    }
}

// seg-add for gather layout (8 nodes x 4 f4 per warp), 4 payloads.
__device__ __forceinline__ void seg_add4(float* baseA, float* baseB, int g,
                                         float4 a0, float4 a1, float4 s0, float4 s1) {
    unsigned lane = threadIdx.x & 31u;
    unsigned f4 = lane & 3u;
    int g0 = __shfl_sync(0xffffffffu, g, 0);
    if (__all_sync(0xffffffffu, g == g0)) {
        redX(a0, 4); redX(a0, 8); redX(a0, 16);
        redX(a1, 4); redX(a1, 8); redX(a1, 16);
        redX(s0, 4); redX(s0, 8); redX(s0, 16);
        redX(s1, 4); redX(s1, 8); redX(s1, 16);
        unsigned grp = lane >> 2;
        if (grp == 0)      at4(baseA + (size_t)g * HID + f4 * 8,     a0);
        else if (grp == 1) at4(baseA + (size_t)g * HID + f4 * 8 + 4, a1);
        else if (grp == 2) at4(baseB + (size_t)g * HID + f4 * 8,     s0);
        else if (grp == 3) at4(baseB + (size_t)g * HID + f4 * 8 + 4, s1);
    } else {
        float* pA = baseA + (size_t)g * HID + f4 * 8;
        float* pB = baseB + (size_t)g * HID + f4 * 8;
        at4(pA, a0); at4(pA + 4, a1);
        at4(pB, s0); at4(pB + 4, s1);
    }
}

// ---------------- setup kernels --------------------------------------------
__global__ void k_zero() {
    int i = blockIdx.x * blockDim.x + threadIdx.x;
    if (i < N_NODES) g_deg[i] = 0;
    if (i < N_GRAPHS) g_cnt[i] = 0.0f;
    if (i < N_GRAPHS * HID) {
        g_gs[0][i] = 0.0f; g_gs[1][i] = 0.0f; g_gs[2][i] = 0.0f;
        g_gv[0][i] = 0.0f; g_gv[1][i] = 0.0f; g_gv[2][i] = 0.0f;
        g_pool[i] = 0.0f;
    }
}

// 4 edges per item, grid-stride, one wave.
__global__ __launch_bounds__(TBG) void k_edges(const int* __restrict__ ei) {
    for (int i = blockIdx.x * TBG + threadIdx.x; i < N_EDGES / 4; i += G_WIDE * TBG) {
        int e = i * 4;
        int4 r = *(const int4*)(ei + e);
        int4 c = *(const int4*)(ei + N_EDGES + e);
#pragma unroll
        for (int j = 0; j < 4; j++) {
            int rr = clampN(j == 0 ? r.x : j == 1 ? r.y : j == 2 ? r.z : r.w);
            int cc = clampN(j == 0 ? c.x : j == 1 ? c.y : j == 2 ? c.z : c.w);
            int s = atomicAdd(&g_deg[cc], 1);
            if (s < CAP) g_csr[(size_t)cc * CAP + s] = rr;
        }
    }
}

// batch decode + counts + dinv + layer-1 projection hs = dinv*(x@W1), fused.
__global__ void k_bdh(const int* __restrict__ batch, const float* __restrict__ x,
                      const float* __restrict__ W) {
    __shared__ float sW[96];                         // W1: [3][32]
    if (threadIdx.x < 96) sW[threadIdx.x] = W[threadIdx.x];
    __syncthreads();
    int n = blockIdx.x * blockDim.x + threadIdx.x;
    if (n >= N_NODES) return;
    int b = min(max(batch[n], 0), N_GRAPHS - 1);
    g_b32[n] = b;
    atomicAdd(&g_cnt[b], 1.0f);
    float di = rsqrtf((float)(g_deg[n] + 1));        // +1 self-loop
    g_dinv[n] = di;
    float x0 = x[n * 3 + 0] * di, x1 = x[n * 3 + 1] * di, x2 = x[n * 3 + 2] * di;
    uint2* dst = g_hq + n * 8;
#pragma unroll
    for (int q = 0; q < 8; q++) {
        float4 h;
        h.x = x0 * sW[q * 4 + 0] + x1 * sW[32 + q * 4 + 0] + x2 * sW[64 + q * 4 + 0];
        h.y = x0 * sW[q * 4 + 1] + x1 * sW[32 + q * 4 + 1] + x2 * sW[64 + q * 4 + 1];
        h.z = x0 * sW[q * 4 + 2] + x1 * sW[32 + q * 4 + 2] + x2 * sW[64 + q * 4 + 2];
        h.w = x0 * sW[q * 4 + 3] + x1 * sW[32 + q * 4 + 3] + x2 * sW[64 + q * 4 + 3];
        dst[q] = pack_h(h);
    }
}

// ---------- GCN gather (4 threads/node, 16B msgs), grid-stride one wave -----
__global__ __launch_bounds__(TBG) void k_gather(const float* __restrict__ bias, int L) {
    const uint4* hq = (const uint4*)g_hq;            // [N_NODES*4], 16B each
    for (int t = blockIdx.x * TBG + threadIdx.x; t < N_NODES * 4; t += G_GATHER * TBG) {
        int n = t >> 2, f4 = t & 3;
        float di = g_dinv[n];
        int d = min(g_deg[n], CAP);
        const int* cp = g_csr + (size_t)n * CAP;
        float4 acc0, acc1;
        unpack2(hq[t], acc0, acc1);                  // self-loop term
        int e = 0;
        for (; e + 4 <= d; e += 4) {
            int4 rr = *(const int4*)(cp + e);
            uint4 q0 = hq[rr.x * 4 + f4];
            uint4 q1 = hq[rr.y * 4 + f4];
            uint4 q2 = hq[rr.z * 4 + f4];
            uint4 q3 = hq[rr.w * 4 + f4];
            acc_add2(acc0, acc1, q0); acc_add2(acc0, acc1, q1);
            acc_add2(acc0, acc1, q2); acc_add2(acc0, acc1, q3);
        }
        for (; e < d; e++) acc_add2(acc0, acc1, hq[cp[e] * 4 + f4]);
        const float4* bp = (const float4*)bias;
        float4 b0 = bp[f4 * 2], b1 = bp[f4 * 2 + 1];
        float4 o0, o1;
        o0.x = b0.x + di * acc0.x; o0.y = b0.y + di * acc0.y;
        o0.z = b0.z + di * acc0.z; o0.w = b0.w + di * acc0.w;
        o1.x = b1.x + di * acc1.x; o1.y = b1.y + di * acc1.y;
        o1.z = b1.z + di * acc1.z; o1.w = b1.w + di * acc1.w;
        g_a[n * 8 + f4 * 2]     = o0;
        g_a[n * 8 + f4 * 2 + 1] = o1;
        float4 s0 = make_float4(o0.x * o0.x, o0.y * o0.y, o0.z * o0.z, o0.w * o0.w);
        float4 s1 = make_float4(o1.x * o1.x, o1.y * o1.y, o1.z * o1.z, o1.w * o1.w);
        seg_add4(g_gs[L], g_gv[L], g_b32[n], o0, o1, s0, s1);
    }
}

// ------- GraphNorm(scale) + residual + relu + {next x@W | pooling} ----------
template <int RES, int POOL, int NEXTW>
__global__ __launch_bounds__(TBY) void k_y(const float* __restrict__ w,
                                           const float* __restrict__ be,
                                           const float* __restrict__ ms,
                                           const float* __restrict__ Wn, int L) {
    __shared__ float4 sw[32 * 8];
    int tid = threadIdx.x;
    if (NEXTW) { sw[tid] = ((const float4*)Wn)[tid]; __syncthreads(); }
    for (int t = blockIdx.x * TBY + tid; t < N_NODES * 8; t += G_WIDE * TBY) {
        int n = t >> 3, f4 = t & 7;
        int g = g_b32[n];
        float rc = 1.0f / fmaxf(g_cnt[g], 1.0f);
        float4 S  = ((const float4*)(g_gs[L] + (size_t)g * HID))[f4];
        float4 SS = ((const float4*)(g_gv[L] + (size_t)g * HID))[f4];
        float4 mv = ((const float4*)ms)[f4];
        float4 w4 = ((const float4*)w)[f4];
        float4 b4 = ((const float4*)be)[f4];
        float4 a = g_a[t];
        float4 y;
        {
            float mean, s, var;
            mean = S.x * rc; s = mean * mv.x; var = SS.x * rc - 2.f * s * mean + s * s;
            y.x = w4.x * (a.x - s) * rsqrtf(var + EPSN) + b4.x;
            mean = S.y * rc; s = mean * mv.y; var = SS.y * rc - 2.f * s * mean + s * s;
            y.y = w4.y * (a.y - s) * rsqrtf(var + EPSN) + b4.y;
            mean = S.z * rc; s = mean * mv.z; var = SS.z * rc - 2.f * s * mean + s * s;
            y.z = w4.z * (a.z - s) * rsqrtf(var + EPSN) + b4.z;
            mean = S.w * rc; s = mean * mv.w; var = SS.w * rc - 2.f * s * mean + s * s;
            y.w = w4.w * (a.w - s) * rsqrtf(var + EPSN) + b4.w;
        }
        if (RES) {
            float4 xo = g_x[t];
            y.x += xo.x; y.y += xo.y; y.z += xo.z; y.w += xo.w;
        }
        y.x = fmaxf(y.x, 0.f); y.y = fmaxf(y.y, 0.f);
        y.z = fmaxf(y.z, 0.f); y.w = fmaxf(y.w, 0.f);
        if (POOL) {
            seg_add(g_pool, g, y);
        } else {
            g_x[t] = y;
        }
        if (NEXTW) {
            unsigned lane = tid & 31u, base = lane & ~7u;
            float4 acc = make_float4(0.f, 0.f, 0.f, 0.f);
#pragma unroll
            for (int j = 0; j < 8; j++) {
                float yx = __shfl_sync(0xffffffffu, y.x, base + j);
                float yy = __shfl_sync(0xffffffffu, y.y, base + j);
                float yz = __shfl_sync(0xffffffffu, y.z, base + j);
                float yw = __shfl_sync(0xffffffffu, y.w, base + j);
                f4fma(acc, yx, sw[(j * 4 + 0) * 8 + f4]);
                f4fma(acc, yy, sw[(j * 4 + 1) * 8 + f4]);
                f4fma(acc, yz, sw[(j * 4 + 2) * 8 + f4]);
                f4fma(acc, yw, sw[(j * 4 + 3) * 8 + f4]);
            }
            float di = g_dinv[n];
            acc.x *= di; acc.y *= di; acc.z *= di; acc.w *= di;
            g_hq[t] = pack_h(acc);
        }
    }
}

// ---------------- head ------------------------------------------------------
__global__ void k_final(const float* __restrict__ Wl, const float* __restrict__ bl,
                        float* __restrict__ out) {
    int i = blockIdx.x * blockDim.x + threadIdx.x;
    if (i >= N_GRAPHS * 3) return;
    int g = i / 3, j = i % 3;
    float rc = 1.0f / fmaxf(g_cnt[g], 1.0f);
    const float* pr = g_pool + (size_t)g * HID;
    float acc = bl[j];
#pragma unroll
    for (int f = 0; f < HID; f++) acc += pr[f] * rc * Wl[f * 3 + j];
    out[i] = acc;
}

// ---------------- launch -----------------------------------------------------
extern "C" void kernel_launch(void* const* d_in, const int* in_sizes, int n_in,
                              void* d_out, int out_size) {
    const float* x     = (const float*)d_in[0];
    const int*   ei    = (const int*)d_in[1];
    const int*   batch = (const int*)d_in[2];
    const float* W1 = (const float*)d_in[3];
    const float* b1 = (const float*)d_in[4];
    const float* W2 = (const float*)d_in[5];
    const float* b2 = (const float*)d_in[6];
    const float* W3 = (const float*)d_in[7];
    const float* b3 = (const float*)d_in[8];
    const float* g1 = (const float*)d_in[9];
    const float* be1 = (const float*)d_in[10];
    const float* ms1 = (const float*)d_in[11];
    const float* g2 = (const float*)d_in[12];
    const float* be2 = (const float*)d_in[13];
    const float* ms2 = (const float*)d_in[14];
    const float* g3 = (const float*)d_in[15];
    const float* be3 = (const float*)d_in[16];
    const float* ms3 = (const float*)d_in[17];
    const float* Wl = (const float*)d_in[18];
    const float* bl = (const float*)d_in[19];
    float* out = (float*)d_out;

    const int GN = (N_NODES + 255) / 256;           // 391
    const int GO = (N_GRAPHS * 3 + 255) / 256;

    k_zero<<<GN, 256>>>();
    k_edges<<<G_WIDE, TBG>>>(ei);
    k_bdh<<<GN, 256>>>(batch, x, W1);

    k_gather<<<G_GATHER, TBG>>>(b1, 0);
    k_y<0, 0, 1><<<G_WIDE, TBY>>>(g1, be1, ms1, W2, 0);

    k_gather<<<G_GATHER, TBG>>>(b2, 1);
    k_y<1, 0, 1><<<G_WIDE, TBY>>>(g2, be2, ms2, W3, 1);

    k_gather<<<G_GATHER, TBG>>>(b3, 2);
    k_y<1, 1, 0><<<G_WIDE, TBY>>>(g3, be3, ms3, W3, 2);

    k_final<<<GO, 256>>>(Wl, bl, out);
}

// round 6
// speedup vs baseline: 1.1829x; 1.1829x over previous
#include <cuda_runtime.h>
#include <cuda_fp16.h>

#define N_NODES 100000
#define N_EDGES 1600000
#define N_GRAPHS 1024
#define HID 32
#define CAP 128
#define EPSN 1e-5f

static_assert((N_NODES * 8) % 256 == 0, "exact grid");
static_assert(N_EDGES % 4 == 0, "edge vec");

// ---------------- scratch (device globals; no allocations allowed) ----------
__device__ int    g_deg[N_NODES];
__device__ int    g_b32[N_NODES];
__device__ float  g_dinv[N_NODES];
__device__ float  g_cnt[N_GRAPHS];
__device__ __align__(16)  int   g_csr[(size_t)N_NODES * CAP];
__device__ __align__(128) uint2 g_hq[N_NODES * 8];   // hs = dinv*(x@W), fp16 x4
__device__ float4 g_a[N_NODES * 8];                  // conv output (fp32)
__device__ float4 g_x[N_NODES * 8];                  // layer activations x1/x2
__device__ __align__(16) float g_gs[3][N_GRAPHS * HID];  // per-graph sums
__device__ __align__(16) float g_gv[3][N_GRAPHS * HID];  // per-graph sum-of-squares
__device__ __align__(16) float g_pool[N_GRAPHS * HID];   // pooling sums

// ---------------- helpers ---------------------------------------------------
__device__ __forceinline__ void f4fma(float4& a, float s, float4 v) {
    a.x += s * v.x; a.y += s * v.y; a.z += s * v.z; a.w += s * v.w;
}
__device__ __forceinline__ void f4add(float4& a, float4 v) {
    a.x += v.x; a.y += v.y; a.z += v.z; a.w += v.w;
}
__device__ __forceinline__ int clampN(int v) { return min(max(v, 0), N_NODES - 1); }

__device__ __forceinline__ float4 unpack_h(uint2 q) {
    __half2 lo = *(__half2*)&q.x, hi = *(__half2*)&q.y;
    float2 a = __half22float2(lo), b = __half22float2(hi);
    return make_float4(a.x, a.y, b.x, b.y);
}
__device__ __forceinline__ uint2 pack_h(float4 v) {
    __half2 lo = __floats2half2_rn(v.x, v.y);
    __half2 hi = __floats2half2_rn(v.z, v.w);
    uint2 q; q.x = *(unsigned*)&lo; q.y = *(unsigned*)&hi; return q;
}

__device__ __forceinline__ void redX(float4& v, int m) {
    v.x += __shfl_xor_sync(0xffffffffu, v.x, m);
    v.y += __shfl_xor_sync(0xffffffffu, v.y, m);
    v.z += __shfl_xor_sync(0xffffffffu, v.z, m);
    v.w += __shfl_xor_sync(0xffffffffu, v.w, m);
}
__device__ __forceinline__ void at4(float* p, float4 v) {
    atomicAdd(p + 0, v.x); atomicAdd(p + 1, v.y);
    atomicAdd(p + 2, v.z); atomicAdd(p + 3, v.w);
}

// seg-add (4 nodes x 8 f4 per warp), single payload.
__device__ __forceinline__ void seg_add(float* base, int g, float4 v) {
    unsigned lane = threadIdx.x & 31u;
    int g0 = __shfl_sync(0xffffffffu, g, 0);
    if (__all_sync(0xffffffffu, g == g0)) {
        redX(v, 8); redX(v, 16);
        if (lane < 8) at4(base + (size_t)g * HID + lane * 4, v);
    } else {
        at4(base + (size_t)g * HID + (lane & 7u) * 4, v);
    }
}

// Dual payload: lanes 0-7 flush A (sum), lanes 8-15 flush B (sumsq).
__device__ __forceinline__ void seg_add2(float* baseA, float* baseB, int g,
                                         float4 va, float4 vb) {
    unsigned lane = threadIdx.x & 31u;
    int g0 = __shfl_sync(0xffffffffu, g, 0);
    if (__all_sync(0xffffffffu, g == g0)) {
        redX(va, 8); redX(va, 16);
        redX(vb, 8); redX(vb, 16);
        if (lane < 8)       at4(baseA + (size_t)g * HID + lane * 4, va);
        else if (lane < 16) at4(baseB + (size_t)g * HID + (lane - 8) * 4, vb);
    } else {
        unsigned f4 = lane & 7u;
        at4(baseA + (size_t)g * HID + f4 * 4, va);
        at4(baseB + (size_t)g * HID + f4 * 4, vb);
    }
}

// ---------------- setup kernels --------------------------------------------
__global__ void k_zero() {
    int i = blockIdx.x * blockDim.x + threadIdx.x;
    if (i < N_NODES) g_deg[i] = 0;
    if (i < N_GRAPHS) g_cnt[i] = 0.0f;
    if (i < N_GRAPHS * HID) {
        g_gs[0][i] = 0.0f; g_gs[1][i] = 0.0f; g_gs[2][i] = 0.0f;
        g_gv[0][i] = 0.0f; g_gv[1][i] = 0.0f; g_gv[2][i] = 0.0f;
        g_pool[i] = 0.0f;
    }
}

// 4 edges per thread, int4-vectorized index loads.
__global__ void k_edges(const int* __restrict__ ei) {
    int i = blockIdx.x * blockDim.x + threadIdx.x;
    int e = i * 4;
    if (e >= N_EDGES) return;
    int4 r = *(const int4*)(ei + e);
    int4 c = *(const int4*)(ei + N_EDGES + e);
#pragma unroll
    for (int j = 0; j < 4; j++) {
        int rr = clampN(j == 0 ? r.x : j == 1 ? r.y : j == 2 ? r.z : r.w);
        int cc = clampN(j == 0 ? c.x : j == 1 ? c.y : j == 2 ? c.z : c.w);
        int s = atomicAdd(&g_deg[cc], 1);
        if (s < CAP) g_csr[(size_t)cc * CAP + s] = rr;
    }
}

// batch decode + counts + dinv + layer-1 projection hs = dinv*(x@W1), fused.
__global__ void k_bdh(const int* __restrict__ batch, const float* __restrict__ x,
                      const float* __restrict__ W) {
    __shared__ float sW[96];                         // W1: [3][32]
    if (threadIdx.x < 96) sW[threadIdx.x] = W[threadIdx.x];
    __syncthreads();
    int n = blockIdx.x * blockDim.x + threadIdx.x;
    if (n >= N_NODES) return;
    int b = min(max(batch[n], 0), N_GRAPHS - 1);
    g_b32[n] = b;
    atomicAdd(&g_cnt[b], 1.0f);
    float di = rsqrtf((float)(g_deg[n] + 1));        // +1 self-loop
    g_dinv[n] = di;
    float x0 = x[n * 3 + 0] * di, x1 = x[n * 3 + 1] * di, x2 = x[n * 3 + 2] * di;
    uint2* dst = g_hq + n * 8;
#pragma unroll
    for (int q = 0; q < 8; q++) {
        float4 h;
        h.x = x0 * sW[q * 4 + 0] + x1 * sW[32 + q * 4 + 0] + x2 * sW[64 + q * 4 + 0];
        h.y = x0 * sW[q * 4 + 1] + x1 * sW[32 + q * 4 + 1] + x2 * sW[64 + q * 4 + 1];
        h.z = x0 * sW[q * 4 + 2] + x1 * sW[32 + q * 4 + 2] + x2 * sW[64 + q * 4 + 2];
        h.w = x0 * sW[q * 4 + 3] + x1 * sW[32 + q * 4 + 3] + x2 * sW[64 + q * 4 + 3];
        dst[q] = pack_h(h);
    }
}

// ---------------- GCN gather (8 threads/node, uint2 msgs) -------------------
// Forced occupancy: 8 CTAs x 256 thr = 2048 threads/SM to hide L2 latency.
__global__ void __launch_bounds__(256, 8)
k_gather(const float* __restrict__ bias, int L) {
    int t = blockIdx.x * 256 + threadIdx.x;          // exact grid: N*8
    int n = t >> 3, f4 = t & 7;
    float di = g_dinv[n];
    int d = min(g_deg[n], CAP);
    const int* cp = g_csr + (size_t)n * CAP;
    float4 acc = unpack_h(g_hq[t]);                  // self-loop term
    int e = 0;
    for (; e + 4 <= d; e += 4) {
        int4 rr = *(const int4*)(cp + e);
        uint2 q0 = g_hq[rr.x * 8 + f4];
        uint2 q1 = g_hq[rr.y * 8 + f4];
        uint2 q2 = g_hq[rr.z * 8 + f4];
        uint2 q3 = g_hq[rr.w * 8 + f4];
        f4add(acc, unpack_h(q0)); f4add(acc, unpack_h(q1));
        f4add(acc, unpack_h(q2)); f4add(acc, unpack_h(q3));
    }
    for (; e < d; e++) f4add(acc, unpack_h(g_hq[cp[e] * 8 + f4]));
    float4 b4 = ((const float4*)bias)[f4];
    float4 out;
    out.x = b4.x + di * acc.x;
    out.y = b4.y + di * acc.y;
    out.z = b4.z + di * acc.z;
    out.w = b4.w + di * acc.w;
    g_a[t] = out;
    float4 sq = make_float4(out.x * out.x, out.y * out.y, out.z * out.z, out.w * out.w);
    seg_add2(g_gs[L], g_gv[L], g_b32[n], out, sq);   // fused mean + var sums
}

// ------- GraphNorm(scale) + residual + relu + {next x@W | pooling} ----------
// var = SS/c - 2*s*mean + s^2, s = mean*ms
template <int RES, int POOL, int NEXTW>
__global__ void k_y(const float* __restrict__ w, const float* __restrict__ be,
                    const float* __restrict__ ms, const float* __restrict__ Wn, int L) {
    __shared__ float4 sw[32 * 8];
    int tid = threadIdx.x;                           // blockDim must be 256
    if (NEXTW) { sw[tid] = ((const float4*)Wn)[tid]; __syncthreads(); }
    int t = blockIdx.x * 256 + tid;                  // exact grid: N*8
    int n = t >> 3, f4 = t & 7;
    int g = g_b32[n];
    float rc = 1.0f / fmaxf(g_cnt[g], 1.0f);
    float4 S  = ((const float4*)(g_gs[L] + (size_t)g * HID))[f4];
    float4 SS = ((const float4*)(g_gv[L] + (size_t)g * HID))[f4];
    float4 mv = ((const float4*)ms)[f4];
    float4 w4 = ((const float4*)w)[f4];
    float4 b4 = ((const float4*)be)[f4];
    float4 a = g_a[t];
    float4 y;
    {
        float mean, s, var;
        mean = S.x * rc; s = mean * mv.x; var = SS.x * rc - 2.f * s * mean + s * s;
        y.x = w4.x * (a.x - s) * rsqrtf(var + EPSN) + b4.x;
        mean = S.y * rc; s = mean * mv.y; var = SS.y * rc - 2.f * s * mean + s * s;
        y.y = w4.y * (a.y - s) * rsqrtf(var + EPSN) + b4.y;
        mean = S.z * rc; s = mean * mv.z; var = SS.z * rc - 2.f * s * mean + s * s;
        y.z = w4.z * (a.z - s) * rsqrtf(var + EPSN) + b4.z;
        mean = S.w * rc; s = mean * mv.w; var = SS.w * rc - 2.f * s * mean + s * s;
        y.w = w4.w * (a.w - s) * rsqrtf(var + EPSN) + b4.w;
    }
    if (RES) {
        float4 xo = g_x[t];
        y.x += xo.x; y.y += xo.y; y.z += xo.z; y.w += xo.w;
    }
    y.x = fmaxf(y.x, 0.f); y.y = fmaxf(y.y, 0.f);
    y.z = fmaxf(y.z, 0.f); y.w = fmaxf(y.w, 0.f);
    if (POOL) {
        seg_add(g_pool, g, y);                       // final layer: only pooling consumes y
    } else {
        g_x[t] = y;                                  // keep for next residual
    }
    if (NEXTW) {
        // next-layer projection via intra-node warp shuffles: h = dinv * (y @ Wn)
        unsigned lane = tid & 31u, base = lane & ~7u;
        float4 acc = make_float4(0.f, 0.f, 0.f, 0.f);
#pragma unroll
        for (int j = 0; j < 8; j++) {
            float yx = __shfl_sync(0xffffffffu, y.x, base + j);
            float yy = __shfl_sync(0xffffffffu, y.y, base + j);
            float yz = __shfl_sync(0xffffffffu, y.z, base + j);
            float yw = __shfl_sync(0xffffffffu, y.w, base + j);
            f4fma(acc, yx, sw[(j * 4 + 0) * 8 + f4]);
            f4fma(acc, yy, sw[(j * 4 + 1) * 8 + f4]);
            f4fma(acc, yz, sw[(j * 4 + 2) * 8 + f4]);
            f4fma(acc, yw, sw[(j * 4 + 3) * 8 + f4]);
        }
        float di = g_dinv[n];
        acc.x *= di; acc.y *= di; acc.z *= di; acc.w *= di;
        g_hq[t] = pack_h(acc);
    }
}

// ---------------- head ------------------------------------------------------
__global__ void k_final(const float* __restrict__ Wl, const float* __restrict__ bl,
                        float* __restrict__ out) {
    int i = blockIdx.x * blockDim.x + threadIdx.x;
    if (i >= N_GRAPHS * 3) return;
    int g = i / 3, j = i % 3;
    float rc = 1.0f / fmaxf(g_cnt[g], 1.0f);
    const float* pr = g_pool + (size_t)g * HID;
    float acc = bl[j];
#pragma unroll
    for (int f = 0; f < HID; f++) acc += pr[f] * rc * Wl[f * 3 + j];
    out[i] = acc;
}

// ---------------- launch -----------------------------------------------------
extern "C" void kernel_launch(void* const* d_in, const int* in_sizes, int n_in,
                              void* d_out, int out_size) {
    const float* x     = (const float*)d_in[0];
    const int*   ei    = (const int*)d_in[1];     // int32 (JAX x64 disabled)
    const int*   batch = (const int*)d_in[2];     // int32
    const float* W1 = (const float*)d_in[3];
    const float* b1 = (const float*)d_in[4];
    const float* W2 = (const float*)d_in[5];
    const float* b2 = (const float*)d_in[6];
    const float* W3 = (const float*)d_in[7];
    const float* b3 = (const float*)d_in[8];
    const float* g1 = (const float*)d_in[9];
    const float* be1 = (const float*)d_in[10];
    const float* ms1 = (const float*)d_in[11];
    const float* g2 = (const float*)d_in[12];
    const float* be2 = (const float*)d_in[13];
    const float* ms2 = (const float*)d_in[14];
    const float* g3 = (const float*)d_in[15];
    const float* be3 = (const float*)d_in[16];
    const float* ms3 = (const float*)d_in[17];
    const float* Wl = (const float*)d_in[18];
    const float* bl = (const float*)d_in[19];
    float* out = (float*)d_out;

    const int GN = (N_NODES + 255) / 256;           // 391
    const int GE = (N_EDGES / 4 + 255) / 256;       // 1563
    const int GF = (N_NODES * 8) / 256;             // 3125 (exact)
    const int GO = (N_GRAPHS * 3 + 255) / 256;

    k_zero<<<GN, 256>>>();
    k_edges<<<GE, 256>>>(ei);
    k_bdh<<<GN, 256>>>(batch, x, W1);

    k_gather<<<GF, 256>>>(b1, 0);
    k_y<0, 0, 1><<<GF, 256>>>(g1, be1, ms1, W2, 0); // gn+relu, emit h2

    k_gather<<<GF, 256>>>(b2, 1);
    k_y<1, 0, 1><<<GF, 256>>>(g2, be2, ms2, W3, 1); // gn+res+relu, emit h3

    k_gather<<<GF, 256>>>(b3, 2);
    k_y<1, 1, 0><<<GF, 256>>>(g3, be3, ms3, W3, 2); // gn+res+relu, pool

    k_final<<<GO, 256>>>(Wl, bl, out);
}